// round 15
// baseline (speedup 1.0000x reference)
#include <cuda_runtime.h>
#include <cstdint>

// query [512,32,256], context [512,2048,256], out [16384,2048] fp32.
#define DD   256
#define RD   2048
#define NT   256           // N-chunk per CTA
#define KT   16            // k-tile
#define NKT  (DD / KT)     // 16
#define CSTR 20            // C tile row stride (floats): 16 data + 4 pad (odd f4 stride)
#define QSTR 34            // Qt row stride (even floats -> 8B-aligned LDS.64 A loads)
#define NCHUNKS (RD / NT)  // 8 CTAs per batch

#define QT_FLOATS (DD * QSTR)            // 8704
#define CT_FLOATS (NT * CSTR)            // 5120 per buffer
#define SMEM_FLOATS (QT_FLOATS + 2 * CT_FLOATS)   // 18944
#define SMEM_BYTES  (SMEM_FLOATS * 4)    // 75776 B -> 3 CTAs/SM

// per-batch completion counters (zero-init at load; last CTA resets -> replay-safe)
__device__ int g_cnt[512];

__device__ __forceinline__ uint64_t pack_dup(float x) {
    uint64_t r;
    asm("mov.b64 %0, {%1, %1};" : "=l"(r) : "f"(x));
    return r;
}
__device__ __forceinline__ void fma2(uint64_t& d, uint64_t a, uint64_t b) {
    asm("fma.rn.f32x2 %0, %1, %2, %0;" : "+l"(d) : "l"(a), "l"(b));
}
__device__ __forceinline__ void unpack2(uint64_t v, float& lo, float& hi) {
    asm("mov.b64 {%0, %1}, %2;" : "=f"(lo), "=f"(hi) : "l"(v));
}
__device__ __forceinline__ void cp16(uint32_t dst, const float* src) {
    asm volatile("cp.async.cg.shared.global [%0], [%1], 16;" :: "r"(dst), "l"(src));
}
#define CP_COMMIT()  asm volatile("cp.async.commit_group;" ::: "memory")
#define CP_WAIT1()   asm volatile("cp.async.wait_group 1;" ::: "memory")

// ============ Fused: scores = Q @ C^T -> out, then sparsemax by last CTA ====
// CTA: 128 threads, tile 32m x 256n, thread tile 16m x 4n (m-paired f32x2).
// 3 CTAs/SM -> 12 warps/SM = 3 warps/SMSP.
__global__ __launch_bounds__(128, 3)
void ruleattn_fused(const float* __restrict__ q,
                    const float* __restrict__ ctx,
                    float* __restrict__ out) {
    extern __shared__ float smem[];
    float* Qt  = smem;                    // [256 k][QSTR] : Qt[k][m], m<32
    float* Cb0 = smem + QT_FLOATS;        // C tile buffer 0 (swizzled)
    float* Cb1 = Cb0 + CT_FLOATS;         // C tile buffer 1
    __shared__ int s_last;

    const uint32_t sbase = (uint32_t)__cvta_generic_to_shared(smem);

    const int tid = threadIdx.x;
    const int b   = blockIdx.y;
    const int r0  = blockIdx.x * NT;

    // ---- stage Q [32][256] coalesced into C buffers (reused before main loop) ----
    {
        const float* qb = q + (size_t)b * 32 * DD;
        #pragma unroll
        for (int it = 0; it < 16; ++it) {
            int i = (tid + 128 * it) * 4;
            *(float4*)(Cb0 + i) = *(const float4*)(qb + i);
        }
    }
    __syncthreads();
    // ---- transpose -> Qt[k][m] (one-time; 2-way conflicts acceptable) ----
    #pragma unroll
    for (int it = 0; it < 64; ++it) {
        int idx = tid + 128 * it;          // idx = m*256 + k
        Qt[(idx & 255) * QSTR + (idx >> 8)] = Cb0[idx];
    }
    __syncthreads();

    const float* cb = ctx + (size_t)b * RD * DD + (size_t)r0 * DD;  // [256][256]

    // issue one k-tile copy: C[r0..r0+255][kt*16 .. +16) -> swizzled smem
    // tile = 256 rows x 4 float4; swizzle: stored col = c ^ ((row>>3)&3)
    auto issue_tile = [&](int kt, const float* buf) {
        uint32_t dstb = sbase + (uint32_t)((buf - smem) * 4);
        #pragma unroll
        for (int i = 0; i < 8; ++i) {
            int f   = i * 128 + tid;       // float4 index in tile (1024 total)
            int row = f >> 2;              // 4 float4 per row
            int c   = f & 3;
            const float* src = cb + row * DD + kt * KT + c * 4;
            uint32_t dst = dstb + (uint32_t)((row * CSTR + ((c ^ ((row >> 3) & 3)) * 4)) * 4);
            cp16(dst, src);
        }
        CP_COMMIT();
    };

    issue_tile(0, Cb0);
    issue_tile(1, Cb1);

    const int mgrp = tid >> 6;             // 0..1 (whole warp same mgrp -> A broadcast)
    const int m0   = mgrp * 16;
    const int nsl  = tid & 63;             // n slot
    const int n0   = nsl * 4;
    const int sw2  = (nsl >> 1) & 3;       // B swizzle key ((row>>3)&3 for rows 4nsl..4nsl+3)

    uint64_t acc[32];                      // [8 m-pairs][4 n]
    #pragma unroll
    for (int i = 0; i < 32; ++i) acc[i] = 0ull;

    for (int kt = 0; kt < NKT; ++kt) {
        CP_WAIT1();                        // tile kt resident (<=1 pending group)
        __syncthreads();
        const float* bp  = (kt & 1) ? Cb1 : Cb0;
        const float* aqt = Qt + kt * KT * QSTR + m0;

        #pragma unroll
        for (int c = 0; c < 4; ++c) {      // 4-k blocks
            // B block: 4 rows x float4 (conflict-free via swizzle)
            const int cc = (c ^ sw2) * 4;
            float4 bq0 = *(const float4*)(bp + (n0 + 0) * CSTR + cc);
            float4 bq1 = *(const float4*)(bp + (n0 + 1) * CSTR + cc);
            float4 bq2 = *(const float4*)(bp + (n0 + 2) * CSTR + cc);
            float4 bq3 = *(const float4*)(bp + (n0 + 3) * CSTR + cc);

            #pragma unroll
            for (int kk = 0; kk < 4; ++kk) {
                const float* aq = aqt + (c * 4 + kk) * QSTR;
                // A m-pairs as LDS.64 (8B-aligned for any even QSTR; broadcast)
                uint64_t A0 = *(const uint64_t*)(aq);        // (m0,   m0+1)
                uint64_t A1 = *(const uint64_t*)(aq + 2);    // (m0+2, m0+3)
                uint64_t A2 = *(const uint64_t*)(aq + 4);
                uint64_t A3 = *(const uint64_t*)(aq + 6);
                uint64_t A4 = *(const uint64_t*)(aq + 8);
                uint64_t A5 = *(const uint64_t*)(aq + 10);
                uint64_t A6 = *(const uint64_t*)(aq + 12);
                uint64_t A7 = *(const uint64_t*)(aq + 14);   // (m0+14, m0+15)
                const float* f0 = &bq0.x; const float* f1 = &bq1.x;
                const float* f2 = &bq2.x; const float* f3 = &bq3.x;
                uint64_t b0 = pack_dup(f0[kk]);
                uint64_t b1 = pack_dup(f1[kk]);
                uint64_t b2 = pack_dup(f2[kk]);
                uint64_t b3 = pack_dup(f3[kk]);
                fma2(acc[ 0], A0, b0); fma2(acc[ 1], A0, b1);
                fma2(acc[ 2], A0, b2); fma2(acc[ 3], A0, b3);
                fma2(acc[ 4], A1, b0); fma2(acc[ 5], A1, b1);
                fma2(acc[ 6], A1, b2); fma2(acc[ 7], A1, b3);
                fma2(acc[ 8], A2, b0); fma2(acc[ 9], A2, b1);
                fma2(acc[10], A2, b2); fma2(acc[11], A2, b3);
                fma2(acc[12], A3, b0); fma2(acc[13], A3, b1);
                fma2(acc[14], A3, b2); fma2(acc[15], A3, b3);
                fma2(acc[16], A4, b0); fma2(acc[17], A4, b1);
                fma2(acc[18], A4, b2); fma2(acc[19], A4, b3);
                fma2(acc[20], A5, b0); fma2(acc[21], A5, b1);
                fma2(acc[22], A5, b2); fma2(acc[23], A5, b3);
                fma2(acc[24], A6, b0); fma2(acc[25], A6, b1);
                fma2(acc[26], A6, b2); fma2(acc[27], A6, b3);
                fma2(acc[28], A7, b0); fma2(acc[29], A7, b1);
                fma2(acc[30], A7, b2); fma2(acc[31], A7, b3);
            }
        }

        __syncthreads();                   // everyone done reading buf[kt&1]
        if (kt + 2 < NKT) issue_tile(kt + 2, (kt & 1) ? Cb1 : Cb0);
        else              CP_COMMIT();     // empty group keeps wait_group accounting
    }

    // ---- epilogue: write scores to gmem (coalesced float4) ----
    float* ob = out + ((size_t)b * 32 + m0) * RD + r0 + n0;
    #pragma unroll
    for (int mp = 0; mp < 8; ++mp) {
        float4 lo, hi;
        unpack2(acc[mp * 4 + 0], lo.x, hi.x);
        unpack2(acc[mp * 4 + 1], lo.y, hi.y);
        unpack2(acc[mp * 4 + 2], lo.z, hi.z);
        unpack2(acc[mp * 4 + 3], lo.w, hi.w);
        *(float4*)(ob + (size_t)(2 * mp)     * RD) = lo;
        *(float4*)(ob + (size_t)(2 * mp + 1) * RD) = hi;
    }

    // ---- completion protocol: last CTA of this batch runs sparsemax ----
    __threadfence();
    __syncthreads();
    if (tid == 0) {
        int old = atomicAdd(&g_cnt[b], 1);
        if (old == NCHUNKS - 1) { g_cnt[b] = 0; s_last = 1; }
        else                    { s_last = 0; }
    }
    __syncthreads();
    if (!s_last) return;

    __threadfence();                       // acquire

    // ---- sparsemax for all 32 rows of batch b (scores hot in L2) ----
    const int w    = tid >> 5;
    const int lane = tid & 31;
    for (int p = 0; p < 8; ++p) {
        const int m = w * 8 + p;
        float4* rp = (float4*)(out + ((size_t)b * 32 + m) * RD);

        float4 v[16];
        #pragma unroll
        for (int t = 0; t < 16; ++t) v[t] = rp[lane + 32 * t];

        float vmax = -1e30f;
        #pragma unroll
        for (int t = 0; t < 16; ++t)
            vmax = fmaxf(vmax, fmaxf(fmaxf(v[t].x, v[t].y), fmaxf(v[t].z, v[t].w)));
        #pragma unroll
        for (int s = 16; s; s >>= 1)
            vmax = fmaxf(vmax, __shfl_xor_sync(0xffffffffu, vmax, s));

        // Newton from below on f(tau)=sum(relu(z-tau))-1 (convex PL, monotone)
        float tau = vmax - 1.0f;
        for (int it = 0; it < 48; ++it) {
            float S = 0.0f; int cnt = 0;
            #pragma unroll
            for (int t = 0; t < 16; ++t) {
                float d;
                d = v[t].x - tau; if (d > 0.0f) { S += d; cnt++; }
                d = v[t].y - tau; if (d > 0.0f) { S += d; cnt++; }
                d = v[t].z - tau; if (d > 0.0f) { S += d; cnt++; }
                d = v[t].w - tau; if (d > 0.0f) { S += d; cnt++; }
            }
            #pragma unroll
            for (int s = 16; s; s >>= 1) {
                S   += __shfl_xor_sync(0xffffffffu, S, s);
                cnt += __shfl_xor_sync(0xffffffffu, cnt, s);
            }
            if (cnt == 0) break;
            float delta = (S - 1.0f) / (float)cnt;
            if (!(delta > 1e-7f * fmaxf(fabsf(tau), 1.0f))) break;
            tau += delta;
        }

        #pragma unroll
        for (int t = 0; t < 16; ++t) {
            float4 o;
            o.x = fmaxf(v[t].x - tau, 0.0f);
            o.y = fmaxf(v[t].y - tau, 0.0f);
            o.z = fmaxf(v[t].z - tau, 0.0f);
            o.w = fmaxf(v[t].w - tau, 0.0f);
            rp[lane + 32 * t] = o;
        }
    }
}

extern "C" void kernel_launch(void* const* d_in, const int* in_sizes, int n_in,
                              void* d_out, int out_size) {
    (void)n_in; (void)out_size;
    const float* q   = (const float*)d_in[0];
    const float* ctx = (const float*)d_in[1];
    float* out = (float*)d_out;

    const int B = in_sizes[0] / (32 * DD);   // 512

    cudaFuncSetAttribute(ruleattn_fused,
                         cudaFuncAttributeMaxDynamicSharedMemorySize, SMEM_BYTES);

    dim3 g1(NCHUNKS, B);                     // 8 x 512 CTAs
    ruleattn_fused<<<g1, 128, SMEM_BYTES>>>(q, ctx, out);
}

// round 17
// speedup vs baseline: 1.0270x; 1.0270x over previous
#include <cuda_runtime.h>
#include <cstdint>

// query [512,32,256], context [512,2048,256], out [16384,2048] fp32.
#define DD   256
#define RD   2048
#define NT   256           // N-chunk per CTA
#define KT   32            // k-tile (k-major rows)
#define NKT  (DD / KT)     // 8
#define CSTR 36            // C tile row stride (floats): 32 + 4 pad
#define QSTR 36            // Qt row stride
#define NCHUNKS (RD / NT)  // 8 CTAs per batch

#define QT_FLOATS (DD * QSTR)            // 9216
#define CT_FLOATS (NT * CSTR)            // 9216 per buffer
#define SMEM_FLOATS (QT_FLOATS + 2 * CT_FLOATS)
#define SMEM_BYTES  (SMEM_FLOATS * 4)    // 110592 B -> 2 CTAs/SM

// per-batch completion counters (zero-init at load; last CTA resets -> replay-safe)
__device__ int g_cnt[512];

__device__ __forceinline__ uint64_t pack_dup(float x) {
    uint64_t r;
    asm("mov.b64 %0, {%1, %1};" : "=l"(r) : "f"(x));
    return r;
}
__device__ __forceinline__ void fma2(uint64_t& d, uint64_t a, uint64_t b) {
    asm("fma.rn.f32x2 %0, %1, %2, %0;" : "+l"(d) : "l"(a), "l"(b));
}
__device__ __forceinline__ void unpack2(uint64_t v, float& lo, float& hi) {
    asm("mov.b64 {%0, %1}, %2;" : "=f"(lo), "=f"(hi) : "l"(v));
}
__device__ __forceinline__ void cp16(uint32_t dst, const float* src) {
    asm volatile("cp.async.cg.shared.global [%0], [%1], 16;" :: "r"(dst), "l"(src));
}
#define CP_COMMIT()  asm volatile("cp.async.commit_group;" ::: "memory")
#define CP_WAIT1()   asm volatile("cp.async.wait_group 1;" ::: "memory")

// ============ Fused: scores = Q @ C^T -> out, then sparsemax by last CTA ====
// CTA: 128 threads, tile 32m x 256n, thread tile 16m x 4n (m-paired f32x2).
// Inner loop software-pipelined: next k-step's A and next block's B are loaded
// into a shadow register set during the current 32-FFMA2 block.
__global__ __launch_bounds__(128, 2)
void ruleattn_fused(const float* __restrict__ q,
                    const float* __restrict__ ctx,
                    float* __restrict__ out) {
    extern __shared__ float smem[];
    float* Qt  = smem;                    // [256 k][QSTR] : Qt[k][m], m<32
    float* Cb0 = smem + QT_FLOATS;        // C tile buffer 0 (k-major swizzled)
    float* Cb1 = Cb0 + CT_FLOATS;         // C tile buffer 1
    __shared__ int s_last;

    const uint32_t sbase = (uint32_t)__cvta_generic_to_shared(smem);

    const int tid = threadIdx.x;
    const int b   = blockIdx.y;
    const int r0  = blockIdx.x * NT;

    // ---- stage Q [32][256] coalesced into Cb0 (reused before main loop) ----
    {
        const float* qb = q + (size_t)b * 32 * DD;
        #pragma unroll
        for (int it = 0; it < 16; ++it) {
            int i = (tid + 128 * it) * 4;
            *(float4*)(Cb0 + i) = *(const float4*)(qb + i);
        }
    }
    __syncthreads();
    // ---- transpose Cb0 -> Qt[k][m] (one-time; conflicts acceptable) ----
    #pragma unroll
    for (int it = 0; it < 64; ++it) {
        int idx = tid + 128 * it;          // idx = m*256 + k
        Qt[(idx & 255) * QSTR + (idx >> 8)] = Cb0[idx];
    }
    __syncthreads();

    const float* cb = ctx + (size_t)b * RD * DD + (size_t)r0 * DD;  // [256][256]

    // issue one k-tile copy: C[r0..r0+255][kt*32 .. +32) -> swizzled k-major smem
    auto issue_tile = [&](int kt, const float* buf) {
        uint32_t dstb = sbase + (uint32_t)((buf - smem) * 4);
        #pragma unroll
        for (int i = 0; i < 16; ++i) {
            int f   = i * 128 + tid;       // float4 index in tile (2048 total)
            int row = f >> 3;              // 8 float4 per row
            int c   = f & 7;
            const float* src = cb + row * DD + kt * KT + c * 4;
            uint32_t dst = dstb + (uint32_t)((row * CSTR + ((c ^ ((row >> 2) & 7)) * 4)) * 4);
            cp16(dst, src);
        }
        CP_COMMIT();
    };

    issue_tile(0, Cb0);
    issue_tile(1, Cb1);

    const int mgrp = tid >> 6;             // 0..1 (whole warp same mgrp -> A broadcast)
    const int m0   = mgrp * 16;
    const int nsl  = tid & 63;             // n slot
    const int n0   = nsl * 4;
    const int sw   = nsl & 7;              // B swizzle key ((n0>>2)&7)

    uint64_t acc[32];                      // [8 m-pairs][4 n]
    #pragma unroll
    for (int i = 0; i < 32; ++i) acc[i] = 0ull;

    for (int kt = 0; kt < NKT; ++kt) {
        CP_WAIT1();                        // tile kt resident (<=1 pending group)
        __syncthreads();
        const float* bp  = (kt & 1) ? Cb1 : Cb0;
        const float* aqt = Qt + kt * KT * QSTR + m0;

        // current + shadow register sets for A (per k-step) and B (per 4-k block)
        float4 Bc0, Bc1, Bc2, Bc3, Bn0, Bn1, Bn2, Bn3;
        ulonglong2 Ac0, Ac1, Ac2, Ac3, An0, An1, An2, An3;
        {
            const int cc = sw * 4;         // block c=0
            Bc0 = *(const float4*)(bp + (n0 + 0) * CSTR + cc);
            Bc1 = *(const float4*)(bp + (n0 + 1) * CSTR + cc);
            Bc2 = *(const float4*)(bp + (n0 + 2) * CSTR + cc);
            Bc3 = *(const float4*)(bp + (n0 + 3) * CSTR + cc);
            Ac0 = *(const ulonglong2*)(aqt);        // m-pairs (m0..m0+3)
            Ac1 = *(const ulonglong2*)(aqt + 4);    // (m0+4..m0+7)
            Ac2 = *(const ulonglong2*)(aqt + 8);    // (m0+8..m0+11)
            Ac3 = *(const ulonglong2*)(aqt + 12);   // (m0+12..m0+15)
        }

        #pragma unroll
        for (int ks = 0; ks < KT; ++ks) {
            const int c  = ks >> 2;        // block index 0..7
            const int kk = ks & 3;

            // load-ahead: next block's B during first k-step of this block
            if (kk == 0 && c + 1 < 8) {
                const int cc = ((c + 1) ^ sw) * 4;
                Bn0 = *(const float4*)(bp + (n0 + 0) * CSTR + cc);
                Bn1 = *(const float4*)(bp + (n0 + 1) * CSTR + cc);
                Bn2 = *(const float4*)(bp + (n0 + 2) * CSTR + cc);
                Bn3 = *(const float4*)(bp + (n0 + 3) * CSTR + cc);
            }
            // load-ahead: next k-step's A
            if (ks + 1 < KT) {
                const float* aq = aqt + (ks + 1) * QSTR;
                An0 = *(const ulonglong2*)(aq);
                An1 = *(const ulonglong2*)(aq + 4);
                An2 = *(const ulonglong2*)(aq + 8);
                An3 = *(const ulonglong2*)(aq + 12);
            }

            // compute with current registers (loaded >=1 iteration ago)
            const float* f0 = (const float*)&Bc0;
            const float* f1 = (const float*)&Bc1;
            const float* f2 = (const float*)&Bc2;
            const float* f3 = (const float*)&Bc3;
            uint64_t b0 = pack_dup(f0[kk]);
            uint64_t b1 = pack_dup(f1[kk]);
            uint64_t b2 = pack_dup(f2[kk]);
            uint64_t b3 = pack_dup(f3[kk]);
            fma2(acc[ 0], Ac0.x, b0); fma2(acc[ 1], Ac0.x, b1);
            fma2(acc[ 2], Ac0.x, b2); fma2(acc[ 3], Ac0.x, b3);
            fma2(acc[ 4], Ac0.y, b0); fma2(acc[ 5], Ac0.y, b1);
            fma2(acc[ 6], Ac0.y, b2); fma2(acc[ 7], Ac0.y, b3);
            fma2(acc[ 8], Ac1.x, b0); fma2(acc[ 9], Ac1.x, b1);
            fma2(acc[10], Ac1.x, b2); fma2(acc[11], Ac1.x, b3);
            fma2(acc[12], Ac1.y, b0); fma2(acc[13], Ac1.y, b1);
            fma2(acc[14], Ac1.y, b2); fma2(acc[15], Ac1.y, b3);
            fma2(acc[16], Ac2.x, b0); fma2(acc[17], Ac2.x, b1);
            fma2(acc[18], Ac2.x, b2); fma2(acc[19], Ac2.x, b3);
            fma2(acc[20], Ac2.y, b0); fma2(acc[21], Ac2.y, b1);
            fma2(acc[22], Ac2.y, b2); fma2(acc[23], Ac2.y, b3);
            fma2(acc[24], Ac3.x, b0); fma2(acc[25], Ac3.x, b1);
            fma2(acc[26], Ac3.x, b2); fma2(acc[27], Ac3.x, b3);
            fma2(acc[28], Ac3.y, b0); fma2(acc[29], Ac3.y, b1);
            fma2(acc[30], Ac3.y, b2); fma2(acc[31], Ac3.y, b3);

            // rotate register sets (renamed away under full unroll)
            Ac0 = An0; Ac1 = An1; Ac2 = An2; Ac3 = An3;
            if (kk == 3) { Bc0 = Bn0; Bc1 = Bn1; Bc2 = Bn2; Bc3 = Bn3; }
        }

        __syncthreads();                   // everyone done reading buf[kt&1]
        if (kt + 2 < NKT) issue_tile(kt + 2, (kt & 1) ? Cb1 : Cb0);
        else              CP_COMMIT();     // empty group keeps wait_group accounting
    }

    // ---- epilogue: write scores to gmem (coalesced float4) ----
    float* ob = out + ((size_t)b * 32 + m0) * RD + r0 + n0;
    #pragma unroll
    for (int mp = 0; mp < 8; ++mp) {
        float4 lo, hi;
        unpack2(acc[mp * 4 + 0], lo.x, hi.x);
        unpack2(acc[mp * 4 + 1], lo.y, hi.y);
        unpack2(acc[mp * 4 + 2], lo.z, hi.z);
        unpack2(acc[mp * 4 + 3], lo.w, hi.w);
        *(float4*)(ob + (size_t)(2 * mp)     * RD) = lo;
        *(float4*)(ob + (size_t)(2 * mp + 1) * RD) = hi;
    }

    // ---- completion protocol: last CTA of this batch runs sparsemax ----
    __threadfence();
    __syncthreads();
    if (tid == 0) {
        int old = atomicAdd(&g_cnt[b], 1);
        if (old == NCHUNKS - 1) { g_cnt[b] = 0; s_last = 1; }
        else                    { s_last = 0; }
    }
    __syncthreads();
    if (!s_last) return;

    __threadfence();                       // acquire

    // ---- sparsemax for all 32 rows of batch b (scores hot in L2) ----
    const int w    = tid >> 5;
    const int lane = tid & 31;
    for (int p = 0; p < 8; ++p) {
        const int m = w * 8 + p;
        float4* rp = (float4*)(out + ((size_t)b * 32 + m) * RD);

        float4 v[16];
        #pragma unroll
        for (int t = 0; t < 16; ++t) v[t] = rp[lane + 32 * t];

        float vmax = -1e30f;
        #pragma unroll
        for (int t = 0; t < 16; ++t)
            vmax = fmaxf(vmax, fmaxf(fmaxf(v[t].x, v[t].y), fmaxf(v[t].z, v[t].w)));
        #pragma unroll
        for (int s = 16; s; s >>= 1)
            vmax = fmaxf(vmax, __shfl_xor_sync(0xffffffffu, vmax, s));

        // Newton from below on f(tau)=sum(relu(z-tau))-1 (convex PL, monotone)
        float tau = vmax - 1.0f;
        for (int it = 0; it < 48; ++it) {
            float S = 0.0f; int cnt = 0;
            #pragma unroll
            for (int t = 0; t < 16; ++t) {
                float d;
                d = v[t].x - tau; if (d > 0.0f) { S += d; cnt++; }
                d = v[t].y - tau; if (d > 0.0f) { S += d; cnt++; }
                d = v[t].z - tau; if (d > 0.0f) { S += d; cnt++; }
                d = v[t].w - tau; if (d > 0.0f) { S += d; cnt++; }
            }
            #pragma unroll
            for (int s = 16; s; s >>= 1) {
                S   += __shfl_xor_sync(0xffffffffu, S, s);
                cnt += __shfl_xor_sync(0xffffffffu, cnt, s);
            }
            if (cnt == 0) break;
            float delta = (S - 1.0f) / (float)cnt;
            if (!(delta > 1e-7f * fmaxf(fabsf(tau), 1.0f))) break;
            tau += delta;
        }

        #pragma unroll
        for (int t = 0; t < 16; ++t) {
            float4 o;
            o.x = fmaxf(v[t].x - tau, 0.0f);
            o.y = fmaxf(v[t].y - tau, 0.0f);
            o.z = fmaxf(v[t].z - tau, 0.0f);
            o.w = fmaxf(v[t].w - tau, 0.0f);
            rp[lane + 32 * t] = o;
        }
    }
}

extern "C" void kernel_launch(void* const* d_in, const int* in_sizes, int n_in,
                              void* d_out, int out_size) {
    (void)n_in; (void)out_size;
    const float* q   = (const float*)d_in[0];
    const float* ctx = (const float*)d_in[1];
    float* out = (float*)d_out;

    const int B = in_sizes[0] / (32 * DD);   // 512

    cudaFuncSetAttribute(ruleattn_fused,
                         cudaFuncAttributeMaxDynamicSharedMemorySize, SMEM_BYTES);

    dim3 g1(NCHUNKS, B);                     // 8 x 512 CTAs
    ruleattn_fused<<<g1, 128, SMEM_BYTES>>>(q, ctx, out);
}